// round 15
// baseline (speedup 1.0000x reference)
#include <cuda_runtime.h>
#include <cuda_bf16.h>
#include <cstdint>

// MaxUnpooling2D scatter-add.
//   updates: f32 [8,128,128,256] = 33,554,432 elems (134 MB)
//   mask:    i32 same shape, values in [0, 2^24)
//   out:     f32 [8,256,256,256] = 134,217,728 elems (536 MB)
//   flat index = mask[i] + batch * 2^22  (batch b targets [b*2^22, b*2^22+2^24))
// Touched range: [0, 46,137,344) words; tail never hit.
//
// R14: SOURCE-batch partitioning (vs R13's target-value partitioning):
//   pass A: batches 0-2, targets subset of [0, 6*2^22)        (100 MB window)
//   pass B: batches 3-5, targets subset of [3*2^22, 9*2^22)   (100 MB)
//   pass C: batches 6-7, targets subset of [6*2^22, 11*2^22)  ( 84 MB)
// Each update read ONCE (268 MB vs R13's 368), no predicates, and each
// pass's target window stays in the ~100MB regime where atomics run at the
// good partitioned rate. Zero schedule interleaves so every word is zeroed
// before any atomic can hit it:
//   zero[0,6) -> A -> zero[6,9) -> B -> zero[9,11) -> C -> zero tail.
// (B's atomics into [3,6) land on lines A already dirtied — zeroed earlier.)

static constexpr int N_OUT   = 134217728;    // output elems (8 * 2^24)
static constexpr int TOUCHED = 46137344;     // 11 * 2^22
static constexpr int BATCH_SHIFT = 22;
static constexpr long long U = 1 << BATCH_SHIFT;   // 2^22

// Zero chunk boundaries (words).
static constexpr int Z0_END = 6 * (1 << BATCH_SHIFT);   // 25,165,824
static constexpr int Z1_END = 9 * (1 << BATCH_SHIFT);   // 37,748,736
// Z2 ends at TOUCHED = 11*2^22.

// Per-pass f4 ranges over the update array (3,145,728 f4 per 3 batches).
static constexpr int F4_PER_BATCH = (1 << BATCH_SHIFT) / 4;   // 1,048,576
static constexpr int A_F4 = 3 * F4_PER_BATCH;                 // 3,145,728
static constexpr int B_F4 = 3 * F4_PER_BATCH;
static constexpr int C_F4 = 2 * F4_PER_BATCH;                 // 2,097,152

__global__ void __launch_bounds__(256) zero_range_kernel(float4* __restrict__ out) {
    int i = blockIdx.x * 256 + threadIdx.x;
    out[i] = make_float4(0.f, 0.f, 0.f, 0.f);
}

// Predicate-free scatter over f4 range [off4, off4 + grid*256).
__global__ void __launch_bounds__(256) scatter_src_kernel(
    const float4* __restrict__ upd4,
    const int4*  __restrict__ mask4,
    float* __restrict__ out,
    int off4)
{
    int i = off4 + blockIdx.x * 256 + threadIdx.x;   // global f4 index
    int4   m = __ldcs(mask4 + i);
    float4 u = __ldcs(upd4 + i);
    // elem index = 4*i -> batch = i >> 20; base = batch << 22
    int base = (i >> (BATCH_SHIFT - 2)) << BATCH_SHIFT;
    atomicAdd(out + (base + m.x), u.x);
    atomicAdd(out + (base + m.y), u.y);
    atomicAdd(out + (base + m.z), u.z);
    atomicAdd(out + (base + m.w), u.w);
}

extern "C" void kernel_launch(void* const* d_in, const int* in_sizes, int n_in,
                              void* d_out, int out_size) {
    const float* updates = (const float*)d_in[0];
    const int*   mask    = (const int*)d_in[1];
    float* out = (float*)d_out;
    const float4* upd4  = (const float4*)updates;
    const int4*   mask4 = (const int4*)mask;

    // zero [0, 6*2^22): 6,291,456 f4 -> 24576 blocks
    zero_range_kernel<<<(Z0_END / 4) / 256, 256>>>((float4*)out);
    // pass A: batches 0-2
    scatter_src_kernel<<<A_F4 / 256, 256>>>(upd4, mask4, out, 0);

    // zero [6*2^22, 9*2^22): 3,145,728 f4 -> 12288 blocks
    zero_range_kernel<<<((Z1_END - Z0_END) / 4) / 256, 256>>>(
        (float4*)(out + Z0_END));
    // pass B: batches 3-5
    scatter_src_kernel<<<B_F4 / 256, 256>>>(upd4, mask4, out, A_F4);

    // zero [9*2^22, TOUCHED): 2,097,152 f4 -> 8192 blocks
    zero_range_kernel<<<((TOUCHED - Z1_END) / 4) / 256, 256>>>(
        (float4*)(out + Z1_END));
    // pass C: batches 6-7
    scatter_src_kernel<<<C_F4 / 256, 256>>>(upd4, mask4, out, A_F4 + B_F4);

    // zero tail [TOUCHED, N_OUT): 22,020,096 f4 -> 86016 blocks
    zero_range_kernel<<<((N_OUT - TOUCHED) / 4) / 256, 256>>>(
        (float4*)(out + TOUCHED));
}